// round 15
// baseline (speedup 1.0000x reference)
#include <cuda_runtime.h>
#include <cuda_fp16.h>
#include <cuda_bf16.h>

#define BB 256
#define OO 10
#define RR 1152
#define II 8
#define DD 16
#define NITER 3
#define NT 256
#define LOG2E 1.4426950408889634f

// Scratch for priors [B, O, R, D] in fp16 — device global (no allocations).
__device__ __half2 g_priors[(size_t)BB * OO * RR * DD / 2];

// ---- packed f32x2 helpers (Blackwell) --------------------------------------
__device__ __forceinline__ unsigned long long pack2(float a, float b) {
    unsigned long long r;
    asm("mov.b64 %0, {%1, %2};" : "=l"(r) : "f"(a), "f"(b));
    return r;
}
__device__ __forceinline__ unsigned long long fma2(unsigned long long a,
                                                   unsigned long long b,
                                                   unsigned long long c) {
    unsigned long long d;
    asm("fma.rn.f32x2 %0, %1, %2, %3;" : "=l"(d) : "l"(a), "l"(b), "l"(c));
    return d;
}
__device__ __forceinline__ unsigned long long mul2(unsigned long long a,
                                                   unsigned long long b) {
    unsigned long long d;
    asm("mul.rn.f32x2 %0, %1, %2;" : "=l"(d) : "l"(a), "l"(b));
    return d;
}
__device__ __forceinline__ void unpack2(unsigned long long v, float& lo, float& hi) {
    asm("mov.b64 {%0, %1}, %2;" : "=f"(lo), "=f"(hi) : "l"(v));
}
__device__ __forceinline__ float ex2f(float x) {
    float y;
    asm("ex2.approx.ftz.f32 %0, %1;" : "=f"(y) : "f"(x));
    return y;
}

// ---------------------------------------------------------------------------
// Kernel 1: priors in fp16 with the o-loop HOISTED INSIDE the CTA.
// CTA covers (rt, bt): stages its 16KB `in` slice once, then loops o=0..9,
// streaming W (.cs) and computing 8 batches per o. This cuts the redundant
// in re-reads (92MB -> 18.8MB of L2 traffic; K1 is LTS-bound).
// Grid: RT(18) * BT(32) = 576 CTAs x 256 threads.
// ---------------------------------------------------------------------------
__global__ __launch_bounds__(256) void priors_kernel(
    const float* __restrict__ in,   // [B, R, I]
    const float* __restrict__ W,    // [O, R, I, D]
    uint2* __restrict__ out)        // [B, O, R, D] as fp16
{
    __shared__ uint4 s_in[1024];    // [b(8)][r(64)][2 x uint4] = 16 KB

    const int tid = threadIdx.x;
    const int c  = tid & 3;
    const int rl = tid >> 2;                  // 0..63
    const int bt = blockIdx.x & 31;           // 32 b-tiles of 8
    const int rt = blockIdx.x >> 5;           // 0..17
    const int r  = rt * 64 + rl;

    // --- Stage in[bt*8 .. +8, rt*64 .. +64, :] into SMEM (coalesced) ---
    {
        const uint4* g4 = reinterpret_cast<const uint4*>(in)
                        + ((size_t)(bt * 8) * RR + rt * 64) * 2;
        #pragma unroll
        for (int s = 0; s < 4; ++s) {
            int idx = s * 256 + tid;          // 0..1023
            int b   = idx >> 7;               // 0..7
            int w   = idx & 127;
            s_in[idx] = g4[(size_t)b * RR * 2 + w];
        }
    }
    __syncthreads();

    const ulonglong2* sin = reinterpret_cast<const ulonglong2*>(s_in)
                          + rl * 2;           // row rl of b=0

    for (int o = 0; o < OO; ++o) {
        // --- W[o,r,i,4c..4c+3], i=0..7, paired over i (.cs: read-once) ---
        const float4* W4 = reinterpret_cast<const float4*>(W);
        const size_t wbase = ((size_t)(o * RR + r) * II) * 4 + c;
        float4 wv[8];
        #pragma unroll
        for (int i = 0; i < 8; ++i) wv[i] = __ldcs(&W4[wbase + (size_t)i * 4]);

        unsigned long long w2[4][4];
        #pragma unroll
        for (int ip = 0; ip < 4; ++ip) {
            const float* f0 = reinterpret_cast<const float*>(&wv[2 * ip]);
            const float* f1 = reinterpret_cast<const float*>(&wv[2 * ip + 1]);
            #pragma unroll
            for (int dl = 0; dl < 4; ++dl)
                w2[ip][dl] = pack2(f0[dl], f1[dl]);
        }

        uint2* outp = out + (((size_t)(bt * 8) * OO + o) * RR + r) * 4 + c;

        #pragma unroll
        for (int b = 0; b < 8; ++b) {
            ulonglong2 q0 = sin[b * 128];         // (in0,in1),(in2,in3)
            ulonglong2 q1 = sin[b * 128 + 1];     // (in4,in5),(in6,in7)

            unsigned long long t0 = mul2(w2[0][0], q0.x);
            unsigned long long t1 = mul2(w2[0][1], q0.x);
            unsigned long long t2 = mul2(w2[0][2], q0.x);
            unsigned long long t3 = mul2(w2[0][3], q0.x);
            t0 = fma2(w2[1][0], q0.y, t0);  t1 = fma2(w2[1][1], q0.y, t1);
            t2 = fma2(w2[1][2], q0.y, t2);  t3 = fma2(w2[1][3], q0.y, t3);
            t0 = fma2(w2[2][0], q1.x, t0);  t1 = fma2(w2[2][1], q1.x, t1);
            t2 = fma2(w2[2][2], q1.x, t2);  t3 = fma2(w2[2][3], q1.x, t3);
            t0 = fma2(w2[3][0], q1.y, t0);  t1 = fma2(w2[3][1], q1.y, t1);
            t2 = fma2(w2[3][2], q1.y, t2);  t3 = fma2(w2[3][3], q1.y, t3);

            float l, h;
            unpack2(t0, l, h); float a0 = l + h;
            unpack2(t1, l, h); float a1 = l + h;
            unpack2(t2, l, h); float a2 = l + h;
            unpack2(t3, l, h); float a3 = l + h;

            __half2 h01 = __floats2half2_rn(a0, a1);
            __half2 h23 = __floats2half2_rn(a2, a3);
            uint2 st;
            st.x = *reinterpret_cast<unsigned*>(&h01);
            st.y = *reinterpret_cast<unsigned*>(&h23);
            outp[(size_t)b * OO * RR * 4] = st;
        }
    }
}

// ---------------------------------------------------------------------------
// Kernel 2 — R14 version VERBATIM (measured 31.1us): dynamic routing,
// iter-0 folded into the tile load, logits in log2 domain (bare ex2).
// ---------------------------------------------------------------------------
__global__ __launch_bounds__(NT) void route_kernel(
    const uint4* __restrict__ priG,   // [B, O, R, D] fp16
    float* __restrict__ out)          // [B, O, 1, D] fp32
{
    extern __shared__ float sm[];
    uint2* priH   = reinterpret_cast<uint2*>(sm);    // RR*4 uint2 = 36864 B
    float* waccF  = sm + RR * DD / 2;                // 8 warps * 16 = 128
    float* wesF   = waccF + 128;                     // 32
    float* svec   = wesF + 32;                       // 16
    float* pscale = svec + 16;                       // 1

    const int tid  = threadIdx.x;
    const int lane = tid & 31;
    const int wid  = tid >> 5;
    const int c    = tid & 3;        // d-chunk 0..3
    const int g    = tid >> 2;       // 0..63 (row group)
    const int pair = blockIdx.x;     // b * O + o

    // ---- Load tile + accumulate iter-0 row sum from the in-flight data ----
    float a8[8] = {0.f, 0.f, 0.f, 0.f, 0.f, 0.f, 0.f, 0.f};
    {
        const uint4* gp = priG + (size_t)pair * (RR * DD / 8);
        uint4* sp = reinterpret_cast<uint4*>(priH);
        #pragma unroll
        for (int j = 0; j < 9; ++j) {
            uint4 v = gp[j * 256 + tid];
            sp[j * 256 + tid] = v;
            float2 f0 = __half22float2(*reinterpret_cast<__half2*>(&v.x));
            float2 f1 = __half22float2(*reinterpret_cast<__half2*>(&v.y));
            float2 f2 = __half22float2(*reinterpret_cast<__half2*>(&v.z));
            float2 f3 = __half22float2(*reinterpret_cast<__half2*>(&v.w));
            a8[0] += f0.x; a8[1] += f0.y; a8[2] += f1.x; a8[3] += f1.y;
            a8[4] += f2.x; a8[5] += f2.y; a8[6] += f3.x; a8[7] += f3.y;
        }
    }
    #pragma unroll
    for (int off = 2; off <= 16; off <<= 1) {
        #pragma unroll
        for (int k = 0; k < 8; ++k)
            a8[k] += __shfl_xor_sync(0xffffffffu, a8[k], off);
    }
    if (lane < 2) {
        float* dst = waccF + wid * 16 + lane * 8;
        #pragma unroll
        for (int k = 0; k < 8; ++k) dst[k] = a8[k];
    }
    __syncthreads();

    // ---- finalize iter 0: svec0 = rowsum/1152, squash scale ----
    if (tid < 16) {
        float s = 0.0f;
        #pragma unroll
        for (int w = 0; w < 8; ++w) s += waccF[w * 16 + tid];
        float sv = s * (1.0f / RR);
        svec[tid] = sv;
        float sq = sv * sv;
        #pragma unroll
        for (int off = 1; off < 16; off <<= 1)
            sq += __shfl_xor_sync(0x0000ffffu, sq, off);
        if (tid == 0)
            pscale[0] = (sq / (1.0f + sq)) * rsqrtf(sq);
    }
    __syncthreads();
    float scale = pscale[0];
    float4 sv4 = reinterpret_cast<float4*>(svec)[c];

    float lgr[18];   // logits in log2 domain
    #pragma unroll
    for (int j = 0; j < 18; ++j) lgr[j] = 0.0f;

    #pragma unroll
    for (int it = 1; it < NITER; ++it) {
        const float scale2 = scale * LOG2E;

        // ---- fused pass: logit update + ex2 + weighted sum ----
        float4 acc = make_float4(0.f, 0.f, 0.f, 0.f);
        float es = 0.0f;
        #pragma unroll
        for (int j = 0; j < 18; ++j) {
            uint2 hv = priH[(j * 64 + g) * 4 + c];
            float2 f0 = __half22float2(*reinterpret_cast<__half2*>(&hv.x));
            float2 f1 = __half22float2(*reinterpret_cast<__half2*>(&hv.y));
            float dt = f0.x * sv4.x + f0.y * sv4.y
                     + f1.x * sv4.z + f1.y * sv4.w;
            dt += __shfl_xor_sync(0xffffffffu, dt, 1);
            dt += __shfl_xor_sync(0xffffffffu, dt, 2);
            lgr[j] += scale2 * dt;
            float e = ex2f(lgr[j]);
            acc.x += e * f0.x; acc.y += e * f0.y;
            acc.z += e * f1.x; acc.w += e * f1.y;
            es += e;
        }
        #pragma unroll
        for (int off = 4; off <= 16; off <<= 1) {
            acc.x += __shfl_xor_sync(0xffffffffu, acc.x, off);
            acc.y += __shfl_xor_sync(0xffffffffu, acc.y, off);
            acc.z += __shfl_xor_sync(0xffffffffu, acc.z, off);
            acc.w += __shfl_xor_sync(0xffffffffu, acc.w, off);
            es    += __shfl_xor_sync(0xffffffffu, es, off);
        }
        if (lane < 4) {
            int i4 = wid * 4 + lane;
            reinterpret_cast<float4*>(waccF)[i4] = acc;
            wesF[i4] = es;
        }
        __syncthreads();

        // ---- finalize svec (16 threads) + squash scale ----
        if (tid < 16) {
            const int c2 = tid >> 2, e2 = tid & 3;
            float s = 0.0f, et = 0.0f;
            #pragma unroll
            for (int w = 0; w < 8; ++w) {
                s  += waccF[(w * 4 + c2) * 4 + e2];
                et += wesF[w * 4 + c2];
            }
            float sv = s / et;
            svec[tid] = sv;
            float sq = sv * sv;
            #pragma unroll
            for (int off = 1; off < 16; off <<= 1)
                sq += __shfl_xor_sync(0x0000ffffu, sq, off);
            if (tid == 0)
                pscale[0] = (sq / (1.0f + sq)) * rsqrtf(sq);
        }
        __syncthreads();
        scale = pscale[0];
        sv4 = reinterpret_cast<float4*>(svec)[c];
    }

    if (tid < 16)
        out[pair * DD + tid] = scale * svec[tid];
}

// ---------------------------------------------------------------------------
extern "C" void kernel_launch(void* const* d_in, const int* in_sizes, int n_in,
                              void* d_out, int out_size)
{
    const float* in = (const float*)d_in[0];   // inputs [B,R,I]
    const float* W  = (const float*)d_in[1];   // route_weights [O,R,I,D]
    float* out = (float*)d_out;                // [B,O,1,D] fp32

    void* pri = nullptr;
    cudaGetSymbolAddress(&pri, g_priors);

    // K1: 576 CTAs x 256 threads (o-loop inside; in staged once per CTA)
    priors_kernel<<<18 * 32, 256>>>(in, W, (uint2*)pri);

    // K2: 2560 CTAs x 256 threads, ~37.6 KB dynamic SMEM (R14, measured)
    const size_t smem = (size_t)(RR * DD / 2 + 128 + 32 + 16 + 8) * sizeof(float);
    cudaFuncSetAttribute(route_kernel,
                         cudaFuncAttributeMaxDynamicSharedMemorySize, (int)smem);
    route_kernel<<<BB * OO, NT, smem>>>((const uint4*)pri, out);
}

// round 16
// speedup vs baseline: 1.1331x; 1.1331x over previous
#include <cuda_runtime.h>
#include <cuda_fp16.h>
#include <cuda_bf16.h>

#define BB 256
#define OO 10
#define RR 1152
#define II 8
#define DD 16
#define NITER 3
#define NT 256
#define LOG2E 1.4426950408889634f

// Scratch for priors [B, O, R, D] in fp16 — device global (no allocations).
__device__ __half2 g_priors[(size_t)BB * OO * RR * DD / 2];

// ---- packed f32x2 helpers (Blackwell) --------------------------------------
__device__ __forceinline__ unsigned long long pack2(float a, float b) {
    unsigned long long r;
    asm("mov.b64 %0, {%1, %2};" : "=l"(r) : "f"(a), "f"(b));
    return r;
}
__device__ __forceinline__ unsigned long long fma2(unsigned long long a,
                                                   unsigned long long b,
                                                   unsigned long long c) {
    unsigned long long d;
    asm("fma.rn.f32x2 %0, %1, %2, %3;" : "=l"(d) : "l"(a), "l"(b), "l"(c));
    return d;
}
__device__ __forceinline__ unsigned long long mul2(unsigned long long a,
                                                   unsigned long long b) {
    unsigned long long d;
    asm("mul.rn.f32x2 %0, %1, %2;" : "=l"(d) : "l"(a), "l"(b));
    return d;
}
__device__ __forceinline__ void unpack2(unsigned long long v, float& lo, float& hi) {
    asm("mov.b64 {%0, %1}, %2;" : "=f"(lo), "=f"(hi) : "l"(v));
}
__device__ __forceinline__ float ex2f(float x) {
    float y;
    asm("ex2.approx.ftz.f32 %0, %1;" : "=f"(y) : "f"(x));
    return y;
}

// ---------------------------------------------------------------------------
// Kernel 1 — R11 shape (proven: 2880 CTAs, 32KB in-staging, 1 o per CTA).
// ONLY change vs R14: b-loop unroll 4 -> 8 (more independent LDS/FMA2/STG
// chains in flight; grid/SMEM/layout untouched).
// ---------------------------------------------------------------------------
__global__ __launch_bounds__(256) void priors_kernel(
    const float* __restrict__ in,   // [B, R, I]
    const float* __restrict__ W,    // [O, R, I, D]
    uint2* __restrict__ out)        // [B, O, R, D] as fp16
{
    __shared__ uint4 s_in[2048];    // [b(16)][r(64)][2 x uint4] = 32 KB

    const int tid = threadIdx.x;
    const int c  = tid & 3;
    const int rl = tid >> 2;                  // 0..63
    const int bt = blockIdx.x & 15;           // 16 b-tiles of 16
    const int rt = (blockIdx.x >> 4) % 18;
    const int o  = (blockIdx.x >> 4) / 18;
    const int r  = rt * 64 + rl;

    // --- Stage in[bt*16 .. +16, rt*64 .. +64, :] into SMEM (coalesced) ---
    {
        const uint4* g4 = reinterpret_cast<const uint4*>(in)
                        + ((size_t)(bt * 16) * RR + rt * 64) * 2;
        #pragma unroll
        for (int s = 0; s < 8; ++s) {
            int idx = s * 256 + tid;          // 0..2047
            int b   = idx >> 7;
            int w   = idx & 127;
            s_in[idx] = g4[(size_t)b * RR * 2 + w];
        }
    }

    // --- W[o,r,i,4c..4c+3], i=0..7, paired over i (.cs: read-once) ---
    const float4* W4 = reinterpret_cast<const float4*>(W);
    const size_t wbase = ((size_t)(o * RR + r) * II) * 4 + c;
    float4 wv[8];
    #pragma unroll
    for (int i = 0; i < 8; ++i) wv[i] = __ldcs(&W4[wbase + (size_t)i * 4]);

    unsigned long long w2[4][4];
    #pragma unroll
    for (int ip = 0; ip < 4; ++ip) {
        const float* f0 = reinterpret_cast<const float*>(&wv[2 * ip]);
        const float* f1 = reinterpret_cast<const float*>(&wv[2 * ip + 1]);
        #pragma unroll
        for (int dl = 0; dl < 4; ++dl)
            w2[ip][dl] = pack2(f0[dl], f1[dl]);
    }
    __syncthreads();

    uint2* outp = out + (((size_t)(bt * 16) * OO + o) * RR + r) * 4 + c;
    const ulonglong2* sin = reinterpret_cast<const ulonglong2*>(s_in)
                          + rl * 2;           // row rl of b=0

    #pragma unroll 8
    for (int b = 0; b < 16; ++b) {
        ulonglong2 q0 = sin[b * 128];         // (in0,in1),(in2,in3)
        ulonglong2 q1 = sin[b * 128 + 1];     // (in4,in5),(in6,in7)

        unsigned long long t0 = mul2(w2[0][0], q0.x);
        unsigned long long t1 = mul2(w2[0][1], q0.x);
        unsigned long long t2 = mul2(w2[0][2], q0.x);
        unsigned long long t3 = mul2(w2[0][3], q0.x);
        t0 = fma2(w2[1][0], q0.y, t0);  t1 = fma2(w2[1][1], q0.y, t1);
        t2 = fma2(w2[1][2], q0.y, t2);  t3 = fma2(w2[1][3], q0.y, t3);
        t0 = fma2(w2[2][0], q1.x, t0);  t1 = fma2(w2[2][1], q1.x, t1);
        t2 = fma2(w2[2][2], q1.x, t2);  t3 = fma2(w2[2][3], q1.x, t3);
        t0 = fma2(w2[3][0], q1.y, t0);  t1 = fma2(w2[3][1], q1.y, t1);
        t2 = fma2(w2[3][2], q1.y, t2);  t3 = fma2(w2[3][3], q1.y, t3);

        float l, h;
        unpack2(t0, l, h); float a0 = l + h;
        unpack2(t1, l, h); float a1 = l + h;
        unpack2(t2, l, h); float a2 = l + h;
        unpack2(t3, l, h); float a3 = l + h;

        __half2 h01 = __floats2half2_rn(a0, a1);
        __half2 h23 = __floats2half2_rn(a2, a3);
        uint2 st;
        st.x = *reinterpret_cast<unsigned*>(&h01);
        st.y = *reinterpret_cast<unsigned*>(&h23);
        *outp = st;
        outp += (size_t)OO * RR * 4;
    }
}

// ---------------------------------------------------------------------------
// Kernel 2 — R14 version VERBATIM (measured 31.1us): dynamic routing,
// iter-0 folded into the tile load, logits in log2 domain (bare ex2).
// ---------------------------------------------------------------------------
__global__ __launch_bounds__(NT) void route_kernel(
    const uint4* __restrict__ priG,   // [B, O, R, D] fp16
    float* __restrict__ out)          // [B, O, 1, D] fp32
{
    extern __shared__ float sm[];
    uint2* priH   = reinterpret_cast<uint2*>(sm);    // RR*4 uint2 = 36864 B
    float* waccF  = sm + RR * DD / 2;                // 8 warps * 16 = 128
    float* wesF   = waccF + 128;                     // 32
    float* svec   = wesF + 32;                       // 16
    float* pscale = svec + 16;                       // 1

    const int tid  = threadIdx.x;
    const int lane = tid & 31;
    const int wid  = tid >> 5;
    const int c    = tid & 3;        // d-chunk 0..3
    const int g    = tid >> 2;       // 0..63 (row group)
    const int pair = blockIdx.x;     // b * O + o

    // ---- Load tile + accumulate iter-0 row sum from the in-flight data ----
    float a8[8] = {0.f, 0.f, 0.f, 0.f, 0.f, 0.f, 0.f, 0.f};
    {
        const uint4* gp = priG + (size_t)pair * (RR * DD / 8);
        uint4* sp = reinterpret_cast<uint4*>(priH);
        #pragma unroll
        for (int j = 0; j < 9; ++j) {
            uint4 v = gp[j * 256 + tid];
            sp[j * 256 + tid] = v;
            float2 f0 = __half22float2(*reinterpret_cast<__half2*>(&v.x));
            float2 f1 = __half22float2(*reinterpret_cast<__half2*>(&v.y));
            float2 f2 = __half22float2(*reinterpret_cast<__half2*>(&v.z));
            float2 f3 = __half22float2(*reinterpret_cast<__half2*>(&v.w));
            a8[0] += f0.x; a8[1] += f0.y; a8[2] += f1.x; a8[3] += f1.y;
            a8[4] += f2.x; a8[5] += f2.y; a8[6] += f3.x; a8[7] += f3.y;
        }
    }
    #pragma unroll
    for (int off = 2; off <= 16; off <<= 1) {
        #pragma unroll
        for (int k = 0; k < 8; ++k)
            a8[k] += __shfl_xor_sync(0xffffffffu, a8[k], off);
    }
    if (lane < 2) {
        float* dst = waccF + wid * 16 + lane * 8;
        #pragma unroll
        for (int k = 0; k < 8; ++k) dst[k] = a8[k];
    }
    __syncthreads();

    // ---- finalize iter 0: svec0 = rowsum/1152, squash scale ----
    if (tid < 16) {
        float s = 0.0f;
        #pragma unroll
        for (int w = 0; w < 8; ++w) s += waccF[w * 16 + tid];
        float sv = s * (1.0f / RR);
        svec[tid] = sv;
        float sq = sv * sv;
        #pragma unroll
        for (int off = 1; off < 16; off <<= 1)
            sq += __shfl_xor_sync(0x0000ffffu, sq, off);
        if (tid == 0)
            pscale[0] = (sq / (1.0f + sq)) * rsqrtf(sq);
    }
    __syncthreads();
    float scale = pscale[0];
    float4 sv4 = reinterpret_cast<float4*>(svec)[c];

    float lgr[18];   // logits in log2 domain
    #pragma unroll
    for (int j = 0; j < 18; ++j) lgr[j] = 0.0f;

    #pragma unroll
    for (int it = 1; it < NITER; ++it) {
        const float scale2 = scale * LOG2E;

        // ---- fused pass: logit update + ex2 + weighted sum ----
        float4 acc = make_float4(0.f, 0.f, 0.f, 0.f);
        float es = 0.0f;
        #pragma unroll
        for (int j = 0; j < 18; ++j) {
            uint2 hv = priH[(j * 64 + g) * 4 + c];
            float2 f0 = __half22float2(*reinterpret_cast<__half2*>(&hv.x));
            float2 f1 = __half22float2(*reinterpret_cast<__half2*>(&hv.y));
            float dt = f0.x * sv4.x + f0.y * sv4.y
                     + f1.x * sv4.z + f1.y * sv4.w;
            dt += __shfl_xor_sync(0xffffffffu, dt, 1);
            dt += __shfl_xor_sync(0xffffffffu, dt, 2);
            lgr[j] += scale2 * dt;
            float e = ex2f(lgr[j]);
            acc.x += e * f0.x; acc.y += e * f0.y;
            acc.z += e * f1.x; acc.w += e * f1.y;
            es += e;
        }
        #pragma unroll
        for (int off = 4; off <= 16; off <<= 1) {
            acc.x += __shfl_xor_sync(0xffffffffu, acc.x, off);
            acc.y += __shfl_xor_sync(0xffffffffu, acc.y, off);
            acc.z += __shfl_xor_sync(0xffffffffu, acc.z, off);
            acc.w += __shfl_xor_sync(0xffffffffu, acc.w, off);
            es    += __shfl_xor_sync(0xffffffffu, es, off);
        }
        if (lane < 4) {
            int i4 = wid * 4 + lane;
            reinterpret_cast<float4*>(waccF)[i4] = acc;
            wesF[i4] = es;
        }
        __syncthreads();

        // ---- finalize svec (16 threads) + squash scale ----
        if (tid < 16) {
            const int c2 = tid >> 2, e2 = tid & 3;
            float s = 0.0f, et = 0.0f;
            #pragma unroll
            for (int w = 0; w < 8; ++w) {
                s  += waccF[(w * 4 + c2) * 4 + e2];
                et += wesF[w * 4 + c2];
            }
            float sv = s / et;
            svec[tid] = sv;
            float sq = sv * sv;
            #pragma unroll
            for (int off = 1; off < 16; off <<= 1)
                sq += __shfl_xor_sync(0x0000ffffu, sq, off);
            if (tid == 0)
                pscale[0] = (sq / (1.0f + sq)) * rsqrtf(sq);
        }
        __syncthreads();
        scale = pscale[0];
        sv4 = reinterpret_cast<float4*>(svec)[c];
    }

    if (tid < 16)
        out[pair * DD + tid] = scale * svec[tid];
}

// ---------------------------------------------------------------------------
extern "C" void kernel_launch(void* const* d_in, const int* in_sizes, int n_in,
                              void* d_out, int out_size)
{
    const float* in = (const float*)d_in[0];   // inputs [B,R,I]
    const float* W  = (const float*)d_in[1];   // route_weights [O,R,I,D]
    float* out = (float*)d_out;                // [B,O,1,D] fp32

    void* pri = nullptr;
    cudaGetSymbolAddress(&pri, g_priors);

    // K1: 2880 CTAs x 256 threads (R11 shape, unroll 8)
    priors_kernel<<<OO * 18 * 16, 256>>>(in, W, (uint2*)pri);

    // K2: 2560 CTAs x 256 threads, ~37.6 KB dynamic SMEM (R14, measured)
    const size_t smem = (size_t)(RR * DD / 2 + 128 + 32 + 16 + 8) * sizeof(float);
    cudaFuncSetAttribute(route_kernel,
                         cudaFuncAttributeMaxDynamicSharedMemorySize, (int)smem);
    route_kernel<<<BB * OO, NT, smem>>>((const uint4*)pri, out);
}

// round 17
// speedup vs baseline: 1.1770x; 1.0387x over previous
#include <cuda_runtime.h>
#include <cuda_fp16.h>
#include <cuda_bf16.h>

#define BB 256
#define OO 10
#define RR 1152
#define II 8
#define DD 16
#define NITER 3
#define NT 256
#define LOG2E 1.4426950408889634f

// Scratch for priors [B, O, R, D] in fp16 — device global (no allocations).
__device__ __half2 g_priors[(size_t)BB * OO * RR * DD / 2];

// ---- packed f32x2 helpers (Blackwell) --------------------------------------
__device__ __forceinline__ unsigned long long pack2(float a, float b) {
    unsigned long long r;
    asm("mov.b64 %0, {%1, %2};" : "=l"(r) : "f"(a), "f"(b));
    return r;
}
__device__ __forceinline__ unsigned long long fma2(unsigned long long a,
                                                   unsigned long long b,
                                                   unsigned long long c) {
    unsigned long long d;
    asm("fma.rn.f32x2 %0, %1, %2, %3;" : "=l"(d) : "l"(a), "l"(b), "l"(c));
    return d;
}
__device__ __forceinline__ unsigned long long mul2(unsigned long long a,
                                                   unsigned long long b) {
    unsigned long long d;
    asm("mul.rn.f32x2 %0, %1, %2;" : "=l"(d) : "l"(a), "l"(b));
    return d;
}
__device__ __forceinline__ void unpack2(unsigned long long v, float& lo, float& hi) {
    asm("mov.b64 {%0, %1}, %2;" : "=f"(lo), "=f"(hi) : "l"(v));
}
__device__ __forceinline__ float ex2f(float x) {
    float y;
    asm("ex2.approx.ftz.f32 %0, %1;" : "=f"(y) : "f"(x));
    return y;
}

// ---------------------------------------------------------------------------
// Kernel 1: priors in fp16. K1 is LTS(L2)-bound: traffic = write 94.5MB +
// W re-reads + in re-reads. This version covers 32 b's per CTA (vs 16),
// halving W re-reads (16x -> 8x): L2 traffic 280 -> 233 MB.
// CTA = (o, rt, bt): 64KB dynamic-SMEM in-staging, 3 CTAs/SM, grid
// O(10)*RT(18)*BT(8) = 1440 CTAs x 256 threads (fully resident, 3.2 waves).
// ---------------------------------------------------------------------------
__global__ __launch_bounds__(256) void priors_kernel(
    const float* __restrict__ in,   // [B, R, I]
    const float* __restrict__ W,    // [O, R, I, D]
    uint2* __restrict__ out)        // [B, O, R, D] as fp16
{
    extern __shared__ uint4 s_in[];           // [b(32)][r(64)][2 x uint4] = 64 KB

    const int tid = threadIdx.x;
    const int c  = tid & 3;
    const int rl = tid >> 2;                  // 0..63
    const int bt = blockIdx.x & 7;            // 8 b-tiles of 32
    const int rt = (blockIdx.x >> 3) % 18;
    const int o  = (blockIdx.x >> 3) / 18;
    const int r  = rt * 64 + rl;

    // --- Stage in[bt*32 .. +32, rt*64 .. +64, :] into SMEM (coalesced) ---
    {
        const uint4* g4 = reinterpret_cast<const uint4*>(in)
                        + ((size_t)(bt * 32) * RR + rt * 64) * 2;
        #pragma unroll
        for (int s = 0; s < 16; ++s) {
            int idx = s * 256 + tid;          // 0..4095
            int b   = idx >> 7;               // 0..31
            int w   = idx & 127;
            s_in[idx] = g4[(size_t)b * RR * 2 + w];
        }
    }

    // --- W[o,r,i,4c..4c+3], i=0..7, paired over i (.cs: read-once) ---
    const float4* W4 = reinterpret_cast<const float4*>(W);
    const size_t wbase = ((size_t)(o * RR + r) * II) * 4 + c;
    float4 wv[8];
    #pragma unroll
    for (int i = 0; i < 8; ++i) wv[i] = __ldcs(&W4[wbase + (size_t)i * 4]);

    unsigned long long w2[4][4];
    #pragma unroll
    for (int ip = 0; ip < 4; ++ip) {
        const float* f0 = reinterpret_cast<const float*>(&wv[2 * ip]);
        const float* f1 = reinterpret_cast<const float*>(&wv[2 * ip + 1]);
        #pragma unroll
        for (int dl = 0; dl < 4; ++dl)
            w2[ip][dl] = pack2(f0[dl], f1[dl]);
    }
    __syncthreads();

    uint2* outp = out + (((size_t)(bt * 32) * OO + o) * RR + r) * 4 + c;
    const ulonglong2* sin = reinterpret_cast<const ulonglong2*>(s_in)
                          + rl * 2;           // row rl of b=0

    #pragma unroll 8
    for (int b = 0; b < 32; ++b) {
        ulonglong2 q0 = sin[b * 128];         // (in0,in1),(in2,in3)
        ulonglong2 q1 = sin[b * 128 + 1];     // (in4,in5),(in6,in7)

        unsigned long long t0 = mul2(w2[0][0], q0.x);
        unsigned long long t1 = mul2(w2[0][1], q0.x);
        unsigned long long t2 = mul2(w2[0][2], q0.x);
        unsigned long long t3 = mul2(w2[0][3], q0.x);
        t0 = fma2(w2[1][0], q0.y, t0);  t1 = fma2(w2[1][1], q0.y, t1);
        t2 = fma2(w2[1][2], q0.y, t2);  t3 = fma2(w2[1][3], q0.y, t3);
        t0 = fma2(w2[2][0], q1.x, t0);  t1 = fma2(w2[2][1], q1.x, t1);
        t2 = fma2(w2[2][2], q1.x, t2);  t3 = fma2(w2[2][3], q1.x, t3);
        t0 = fma2(w2[3][0], q1.y, t0);  t1 = fma2(w2[3][1], q1.y, t1);
        t2 = fma2(w2[3][2], q1.y, t2);  t3 = fma2(w2[3][3], q1.y, t3);

        float l, h;
        unpack2(t0, l, h); float a0 = l + h;
        unpack2(t1, l, h); float a1 = l + h;
        unpack2(t2, l, h); float a2 = l + h;
        unpack2(t3, l, h); float a3 = l + h;

        __half2 h01 = __floats2half2_rn(a0, a1);
        __half2 h23 = __floats2half2_rn(a2, a3);
        uint2 st;
        st.x = *reinterpret_cast<unsigned*>(&h01);
        st.y = *reinterpret_cast<unsigned*>(&h23);
        *outp = st;
        outp += (size_t)OO * RR * 4;
    }
}

// ---------------------------------------------------------------------------
// Kernel 2 — R14/R16 version VERBATIM (measured 31.1-31.8us): dynamic
// routing, iter-0 folded into the tile load, logits in log2 domain (ex2).
// ---------------------------------------------------------------------------
__global__ __launch_bounds__(NT) void route_kernel(
    const uint4* __restrict__ priG,   // [B, O, R, D] fp16
    float* __restrict__ out)          // [B, O, 1, D] fp32
{
    extern __shared__ float sm[];
    uint2* priH   = reinterpret_cast<uint2*>(sm);    // RR*4 uint2 = 36864 B
    float* waccF  = sm + RR * DD / 2;                // 8 warps * 16 = 128
    float* wesF   = waccF + 128;                     // 32
    float* svec   = wesF + 32;                       // 16
    float* pscale = svec + 16;                       // 1

    const int tid  = threadIdx.x;
    const int lane = tid & 31;
    const int wid  = tid >> 5;
    const int c    = tid & 3;        // d-chunk 0..3
    const int g    = tid >> 2;       // 0..63 (row group)
    const int pair = blockIdx.x;     // b * O + o

    // ---- Load tile + accumulate iter-0 row sum from the in-flight data ----
    float a8[8] = {0.f, 0.f, 0.f, 0.f, 0.f, 0.f, 0.f, 0.f};
    {
        const uint4* gp = priG + (size_t)pair * (RR * DD / 8);
        uint4* sp = reinterpret_cast<uint4*>(priH);
        #pragma unroll
        for (int j = 0; j < 9; ++j) {
            uint4 v = gp[j * 256 + tid];
            sp[j * 256 + tid] = v;
            float2 f0 = __half22float2(*reinterpret_cast<__half2*>(&v.x));
            float2 f1 = __half22float2(*reinterpret_cast<__half2*>(&v.y));
            float2 f2 = __half22float2(*reinterpret_cast<__half2*>(&v.z));
            float2 f3 = __half22float2(*reinterpret_cast<__half2*>(&v.w));
            a8[0] += f0.x; a8[1] += f0.y; a8[2] += f1.x; a8[3] += f1.y;
            a8[4] += f2.x; a8[5] += f2.y; a8[6] += f3.x; a8[7] += f3.y;
        }
    }
    #pragma unroll
    for (int off = 2; off <= 16; off <<= 1) {
        #pragma unroll
        for (int k = 0; k < 8; ++k)
            a8[k] += __shfl_xor_sync(0xffffffffu, a8[k], off);
    }
    if (lane < 2) {
        float* dst = waccF + wid * 16 + lane * 8;
        #pragma unroll
        for (int k = 0; k < 8; ++k) dst[k] = a8[k];
    }
    __syncthreads();

    // ---- finalize iter 0: svec0 = rowsum/1152, squash scale ----
    if (tid < 16) {
        float s = 0.0f;
        #pragma unroll
        for (int w = 0; w < 8; ++w) s += waccF[w * 16 + tid];
        float sv = s * (1.0f / RR);
        svec[tid] = sv;
        float sq = sv * sv;
        #pragma unroll
        for (int off = 1; off < 16; off <<= 1)
            sq += __shfl_xor_sync(0x0000ffffu, sq, off);
        if (tid == 0)
            pscale[0] = (sq / (1.0f + sq)) * rsqrtf(sq);
    }
    __syncthreads();
    float scale = pscale[0];
    float4 sv4 = reinterpret_cast<float4*>(svec)[c];

    float lgr[18];   // logits in log2 domain
    #pragma unroll
    for (int j = 0; j < 18; ++j) lgr[j] = 0.0f;

    #pragma unroll
    for (int it = 1; it < NITER; ++it) {
        const float scale2 = scale * LOG2E;

        // ---- fused pass: logit update + ex2 + weighted sum ----
        float4 acc = make_float4(0.f, 0.f, 0.f, 0.f);
        float es = 0.0f;
        #pragma unroll
        for (int j = 0; j < 18; ++j) {
            uint2 hv = priH[(j * 64 + g) * 4 + c];
            float2 f0 = __half22float2(*reinterpret_cast<__half2*>(&hv.x));
            float2 f1 = __half22float2(*reinterpret_cast<__half2*>(&hv.y));
            float dt = f0.x * sv4.x + f0.y * sv4.y
                     + f1.x * sv4.z + f1.y * sv4.w;
            dt += __shfl_xor_sync(0xffffffffu, dt, 1);
            dt += __shfl_xor_sync(0xffffffffu, dt, 2);
            lgr[j] += scale2 * dt;
            float e = ex2f(lgr[j]);
            acc.x += e * f0.x; acc.y += e * f0.y;
            acc.z += e * f1.x; acc.w += e * f1.y;
            es += e;
        }
        #pragma unroll
        for (int off = 4; off <= 16; off <<= 1) {
            acc.x += __shfl_xor_sync(0xffffffffu, acc.x, off);
            acc.y += __shfl_xor_sync(0xffffffffu, acc.y, off);
            acc.z += __shfl_xor_sync(0xffffffffu, acc.z, off);
            acc.w += __shfl_xor_sync(0xffffffffu, acc.w, off);
            es    += __shfl_xor_sync(0xffffffffu, es, off);
        }
        if (lane < 4) {
            int i4 = wid * 4 + lane;
            reinterpret_cast<float4*>(waccF)[i4] = acc;
            wesF[i4] = es;
        }
        __syncthreads();

        // ---- finalize svec (16 threads) + squash scale ----
        if (tid < 16) {
            const int c2 = tid >> 2, e2 = tid & 3;
            float s = 0.0f, et = 0.0f;
            #pragma unroll
            for (int w = 0; w < 8; ++w) {
                s  += waccF[(w * 4 + c2) * 4 + e2];
                et += wesF[w * 4 + c2];
            }
            float sv = s / et;
            svec[tid] = sv;
            float sq = sv * sv;
            #pragma unroll
            for (int off = 1; off < 16; off <<= 1)
                sq += __shfl_xor_sync(0x0000ffffu, sq, off);
            if (tid == 0)
                pscale[0] = (sq / (1.0f + sq)) * rsqrtf(sq);
        }
        __syncthreads();
        scale = pscale[0];
        sv4 = reinterpret_cast<float4*>(svec)[c];
    }

    if (tid < 16)
        out[pair * DD + tid] = scale * svec[tid];
}

// ---------------------------------------------------------------------------
extern "C" void kernel_launch(void* const* d_in, const int* in_sizes, int n_in,
                              void* d_out, int out_size)
{
    const float* in = (const float*)d_in[0];   // inputs [B,R,I]
    const float* W  = (const float*)d_in[1];   // route_weights [O,R,I,D]
    float* out = (float*)d_out;                // [B,O,1,D] fp32

    void* pri = nullptr;
    cudaGetSymbolAddress(&pri, g_priors);

    // K1: 1440 CTAs x 256 threads, 64KB dynamic SMEM (32 b's per CTA)
    const size_t smem1 = 32 * 64 * 32;         // 65536 B
    cudaFuncSetAttribute(priors_kernel,
                         cudaFuncAttributeMaxDynamicSharedMemorySize, (int)smem1);
    priors_kernel<<<OO * 18 * 8, 256, smem1>>>(in, W, (uint2*)pri);

    // K2: 2560 CTAs x 256 threads, ~37.6 KB dynamic SMEM (R14/R16, measured)
    const size_t smem2 = (size_t)(RR * DD / 2 + 128 + 32 + 16 + 8) * sizeof(float);
    cudaFuncSetAttribute(route_kernel,
                         cudaFuncAttributeMaxDynamicSharedMemorySize, (int)smem2);
    route_kernel<<<BB * OO, NT, smem2>>>((const uint4*)pri, out);
}